// round 5
// baseline (speedup 1.0000x reference)
#include <cuda_runtime.h>
#include <math.h>

#define N_NODES 100000
#define N_EDGES 1600000
#define NFEAT   512
#define NHID    128
#define NCLASS  40

// ---------------- static scratch (no allocation allowed) ----------------
__device__ float d_H1[(size_t)N_NODES * NHID];    // features @ W1
__device__ float d_X1[(size_t)N_NODES * NHID];    // relu(agg1 + b1)
__device__ float d_H2[(size_t)N_NODES * NCLASS];  // X1 @ W2
__device__ int   d_deg[N_NODES];
__device__ int   d_cursor[N_NODES];
__device__ int   d_rowptr[N_NODES + 1];
__device__ int   d_blk[128];
__device__ int   d_csr_src[N_EDGES];
__device__ float d_csr_w[N_EDGES];

// ---------------- f32x2 helpers (packed dual-fp32 pipe) ----------------
__device__ __forceinline__ unsigned long long pk2(float x, float y) {
    unsigned long long r;
    asm("mov.b64 %0, {%1, %2};" : "=l"(r) : "f"(x), "f"(y));
    return r;
}
__device__ __forceinline__ void fma2(unsigned long long &d, unsigned long long a, unsigned long long b) {
    asm("fma.rn.f32x2 %0, %1, %2, %0;" : "+l"(d) : "l"(a), "l"(b));
}
__device__ __forceinline__ float2 upk(unsigned long long v) {
    float x, y;
    asm("mov.b64 {%0, %1}, %2;" : "=f"(x), "=f"(y) : "l"(v));
    return make_float2(x, y);
}

// ---------------- CSR build ----------------
__global__ void k_zero_counts() {
    int i = blockIdx.x * blockDim.x + threadIdx.x;
    if (i < N_NODES) { d_deg[i] = 0; d_cursor[i] = 0; }
}

__global__ void k_hist(const int* __restrict__ dst) {
    int e = blockIdx.x * blockDim.x + threadIdx.x;
    if (e < N_EDGES) atomicAdd(&d_deg[dst[e]], 1);
}

#define SCAN_CHUNK 1024
#define SCAN_BLOCKS ((N_NODES + SCAN_CHUNK - 1) / SCAN_CHUNK)   // 98

__global__ void k_scan1() {
    __shared__ int sm[SCAN_CHUNK];
    int i = blockIdx.x * SCAN_CHUNK + threadIdx.x;
    int v = (i < N_NODES) ? d_deg[i] : 0;
    sm[threadIdx.x] = v;
    __syncthreads();
    for (int off = 1; off < SCAN_CHUNK; off <<= 1) {
        int t = (threadIdx.x >= off) ? sm[threadIdx.x - off] : 0;
        __syncthreads();
        sm[threadIdx.x] += t;
        __syncthreads();
    }
    if (i < N_NODES) d_rowptr[i] = sm[threadIdx.x] - v;   // exclusive
    if (threadIdx.x == SCAN_CHUNK - 1) d_blk[blockIdx.x] = sm[threadIdx.x];
}

__global__ void k_scan2() {
    // single thread: 98 elements, trivial
    int acc = 0;
    for (int b = 0; b < SCAN_BLOCKS; b++) { int t = d_blk[b]; d_blk[b] = acc; acc += t; }
}

__global__ void k_scan3() {
    int i = blockIdx.x * blockDim.x + threadIdx.x;
    if (i < N_NODES) d_rowptr[i] += d_blk[i / SCAN_CHUNK];
    if (i == N_NODES) d_rowptr[N_NODES] = N_EDGES;
}

__global__ void k_fill(const int* __restrict__ src, const int* __restrict__ dst,
                       const float* __restrict__ w) {
    int e = blockIdx.x * blockDim.x + threadIdx.x;
    if (e < N_EDGES) {
        int d = dst[e];
        int pos = d_rowptr[d] + atomicAdd(&d_cursor[d], 1);
        d_csr_src[pos] = src[e];
        d_csr_w[pos]   = w[e];
    }
}

// ---------------- GEMM1: H1 = features @ W1   [100000,512]x[512,128] ----------------
// BM=128, BN=128, BK=16, 256 threads, 8x8 per-thread tile, f32x2 accumulators.
__global__ void __launch_bounds__(256) k_gemm1(const float* __restrict__ A,
                                               const float* __restrict__ B) {
    __shared__ float As[16][128];   // [k][m]
    __shared__ float Bs[16][128];   // [k][n]
    const int tid = threadIdx.x;
    const int m0  = blockIdx.x * 128;
    const int tx  = tid & 15;       // col group
    const int ty  = tid >> 4;       // row group
    const int tm  = ty * 8;
    const int tn  = tx * 8;

    unsigned long long acc[8][4];
    #pragma unroll
    for (int i = 0; i < 8; i++)
        #pragma unroll
        for (int j = 0; j < 4; j++) acc[i][j] = 0ull;

    const int ar = tid >> 2;          // 0..63
    const int ac = (tid & 3) * 4;     // 0,4,8,12

    for (int k0 = 0; k0 < NFEAT; k0 += 16) {
        // load A tile (128x16), transposed into As[k][m]
        #pragma unroll
        for (int t = 0; t < 2; t++) {
            int mrow = ar + t * 64;
            int m = m0 + mrow;
            float4 v = make_float4(0.f, 0.f, 0.f, 0.f);
            if (m < N_NODES)
                v = *reinterpret_cast<const float4*>(A + (size_t)m * NFEAT + k0 + ac);
            As[ac + 0][mrow] = v.x;
            As[ac + 1][mrow] = v.y;
            As[ac + 2][mrow] = v.z;
            As[ac + 3][mrow] = v.w;
        }
        // load B tile (16x128)
        #pragma unroll
        for (int t = 0; t < 2; t++) {
            int idx = tid + t * 256;            // 0..511 float4s
            int row = idx >> 5;
            int col = (idx & 31) * 4;
            float4 v = *reinterpret_cast<const float4*>(B + (size_t)(k0 + row) * NHID + col);
            *reinterpret_cast<float4*>(&Bs[row][col]) = v;
        }
        __syncthreads();

        #pragma unroll
        for (int k = 0; k < 16; k++) {
            float4 a0 = *reinterpret_cast<const float4*>(&As[k][tm]);
            float4 a1 = *reinterpret_cast<const float4*>(&As[k][tm + 4]);
            float4 b0 = *reinterpret_cast<const float4*>(&Bs[k][tn]);
            float4 b1 = *reinterpret_cast<const float4*>(&Bs[k][tn + 4]);
            unsigned long long bp[4];
            bp[0] = pk2(b0.x, b0.y); bp[1] = pk2(b0.z, b0.w);
            bp[2] = pk2(b1.x, b1.y); bp[3] = pk2(b1.z, b1.w);
            float av[8] = {a0.x, a0.y, a0.z, a0.w, a1.x, a1.y, a1.z, a1.w};
            #pragma unroll
            for (int i = 0; i < 8; i++) {
                unsigned long long ad = pk2(av[i], av[i]);
                #pragma unroll
                for (int j = 0; j < 4; j++) fma2(acc[i][j], ad, bp[j]);
            }
        }
        __syncthreads();
    }

    #pragma unroll
    for (int i = 0; i < 8; i++) {
        int m = m0 + tm + i;
        if (m < N_NODES) {
            float2 p0 = upk(acc[i][0]), p1 = upk(acc[i][1]);
            float2 p2 = upk(acc[i][2]), p3 = upk(acc[i][3]);
            float* c = d_H1 + (size_t)m * NHID + tn;
            *reinterpret_cast<float4*>(c)     = make_float4(p0.x, p0.y, p1.x, p1.y);
            *reinterpret_cast<float4*>(c + 4) = make_float4(p2.x, p2.y, p3.x, p3.y);
        }
    }
}

// ---------------- Aggregation layer 1 + bias + relu: warp per node ----------------
__global__ void __launch_bounds__(256) k_agg1(const float* __restrict__ b1) {
    int node = blockIdx.x * 8 + (threadIdx.x >> 5);
    if (node >= N_NODES) return;
    int lane = threadIdx.x & 31;
    int beg = d_rowptr[node], end = d_rowptr[node + 1];
    float4 acc = make_float4(0.f, 0.f, 0.f, 0.f);
    for (int e = beg; e < end; e++) {
        int s = d_csr_src[e];
        float w = d_csr_w[e];
        float4 v = *reinterpret_cast<const float4*>(d_H1 + (size_t)s * NHID + lane * 4);
        acc.x = fmaf(w, v.x, acc.x);
        acc.y = fmaf(w, v.y, acc.y);
        acc.z = fmaf(w, v.z, acc.z);
        acc.w = fmaf(w, v.w, acc.w);
    }
    float4 bb = reinterpret_cast<const float4*>(b1)[lane];
    acc.x = fmaxf(acc.x + bb.x, 0.f);
    acc.y = fmaxf(acc.y + bb.y, 0.f);
    acc.z = fmaxf(acc.z + bb.z, 0.f);
    acc.w = fmaxf(acc.w + bb.w, 0.f);
    *reinterpret_cast<float4*>(d_X1 + (size_t)node * NHID + lane * 4) = acc;
}

// ---------------- GEMM2: H2 = X1 @ W2   [100000,128]x[128,40] ----------------
__global__ void __launch_bounds__(256) k_gemm2(const float* __restrict__ W2) {
    __shared__ float w[NHID * NCLASS];   // [k][c], 20KB
    for (int i = threadIdx.x; i < NHID * NCLASS; i += 256) w[i] = W2[i];
    __syncthreads();

    int n = blockIdx.x * blockDim.x + threadIdx.x;
    if (n >= N_NODES) return;

    unsigned long long acc[NCLASS / 2];
    #pragma unroll
    for (int j = 0; j < NCLASS / 2; j++) acc[j] = 0ull;

    const float4* xr = reinterpret_cast<const float4*>(d_X1 + (size_t)n * NHID);
    #pragma unroll 4
    for (int k4 = 0; k4 < NHID / 4; k4++) {
        float4 xv = xr[k4];
        float xs[4] = {xv.x, xv.y, xv.z, xv.w};
        #pragma unroll
        for (int q = 0; q < 4; q++) {
            int k = k4 * 4 + q;
            unsigned long long xd = pk2(xs[q], xs[q]);
            const unsigned long long* wr =
                reinterpret_cast<const unsigned long long*>(&w[k * NCLASS]);
            #pragma unroll
            for (int j = 0; j < NCLASS / 2; j++) fma2(acc[j], xd, wr[j]);
        }
    }
    float* o = d_H2 + (size_t)n * NCLASS;
    #pragma unroll
    for (int j = 0; j < NCLASS / 2; j++) {
        float2 p = upk(acc[j]);
        o[2 * j] = p.x; o[2 * j + 1] = p.y;
    }
}

// ---------------- Aggregation layer 2 + bias + log_softmax: warp per node ----------------
__global__ void __launch_bounds__(256) k_agg2_lsm(const float* __restrict__ b2,
                                                  float* __restrict__ out) {
    int node = blockIdx.x * 8 + (threadIdx.x >> 5);
    if (node >= N_NODES) return;
    int lane = threadIdx.x & 31;
    bool has1 = lane < (NCLASS - 32);   // lanes 0..7 cover cols 32..39
    int beg = d_rowptr[node], end = d_rowptr[node + 1];
    float a0 = 0.f, a1 = 0.f;
    for (int e = beg; e < end; e++) {
        int s = d_csr_src[e];
        float w = d_csr_w[e];
        const float* r = d_H2 + (size_t)s * NCLASS;
        a0 = fmaf(w, r[lane], a0);
        if (has1) a1 = fmaf(w, r[32 + lane], a1);
    }
    a0 += b2[lane];
    if (has1) a1 += b2[32 + lane];

    float m = has1 ? fmaxf(a0, a1) : a0;
    #pragma unroll
    for (int off = 16; off; off >>= 1) m = fmaxf(m, __shfl_xor_sync(0xffffffffu, m, off));
    float s = expf(a0 - m) + (has1 ? expf(a1 - m) : 0.f);
    #pragma unroll
    for (int off = 16; off; off >>= 1) s += __shfl_xor_sync(0xffffffffu, s, off);
    float l = m + logf(s);

    float* o = out + (size_t)node * NCLASS;
    o[lane] = a0 - l;
    if (has1) o[32 + lane] = a1 - l;
}

// ---------------- launch ----------------
extern "C" void kernel_launch(void* const* d_in, const int* in_sizes, int n_in,
                              void* d_out, int out_size) {
    const float* features = (const float*)d_in[0];
    const int*   edge_src = (const int*)d_in[1];
    const int*   edge_dst = (const int*)d_in[2];
    const float* edge_w   = (const float*)d_in[3];
    const float* W1       = (const float*)d_in[4];
    const float* b1       = (const float*)d_in[5];
    const float* W2       = (const float*)d_in[6];
    const float* b2       = (const float*)d_in[7];
    float* out = (float*)d_out;

    // CSR build
    k_zero_counts<<<(N_NODES + 255) / 256, 256>>>();
    k_hist<<<(N_EDGES + 255) / 256, 256>>>(edge_dst);
    k_scan1<<<SCAN_BLOCKS, SCAN_CHUNK>>>();
    k_scan2<<<1, 1>>>();
    k_scan3<<<(N_NODES + 256) / 256, 256>>>();
    k_fill<<<(N_EDGES + 255) / 256, 256>>>(edge_src, edge_dst, edge_w);

    // layer 1
    k_gemm1<<<(N_NODES + 127) / 128, 256>>>(features, W1);
    k_agg1<<<(N_NODES + 7) / 8, 256>>>(b1);

    // layer 2
    k_gemm2<<<(N_NODES + 255) / 256, 256>>>(W2);
    k_agg2_lsm<<<(N_NODES + 7) / 8, 256>>>(b2, out);
}